// round 15
// baseline (speedup 1.0000x reference)
#include <cuda_runtime.h>
#include <cuda_fp16.h>
#include <math.h>
#include <stdint.h>

// Problem dims
#define Bsz 256
#define Ssz 128
#define Tsz 64
#define Isz 63
#define Hsz 1024
#define G3  (3*Hsz)   // 3072
#define KP  64        // padded input dim

// Scratch (device globals — no allocations allowed)
__device__ __half g_GIh[(size_t)Bsz * Ssz * G3];    // encoder gi_all fp16
__device__ __half g_G2h[(size_t)Bsz * Tsz * G3];    // decoder gi fp16
__device__ float g_GH[(size_t)Bsz * G3];            // decoder gh (B, 3H)
__device__ float g_states[(size_t)Bsz * Tsz * Hsz]; // decoder states (B*T, H)
__device__ float g_hbuf[2][(size_t)Bsz * Hsz];      // hidden fp32, double buffered
__device__ __half g_hh[2][(size_t)Bsz * Hsz];       // h fp16
__device__ __half g_wq[(size_t)G3 * Hsz];           // enc Whh fp16
__device__ __half g_encin_h[(size_t)Bsz * Ssz * KP];// enc inputs fp16, padded K=64
__device__ __half g_decin_h[(size_t)Bsz * Tsz * KP];// dec inputs fp16, padded
__device__ __half g_wih1_h[(size_t)G3 * KP];        // enc Wih fp16, padded
__device__ __half g_wih2_h[(size_t)G3 * KP];        // dec Wih fp16, padded

// ---------------------------------------------------------------------------
__device__ __forceinline__ uint32_t smem_u32(const void* p) {
    uint32_t a;
    asm("{ .reg .u64 t; cvta.to.shared.u64 t, %1; cvt.u32.u64 %0, t; }"
        : "=r"(a) : "l"(p));
    return a;
}
__device__ __forceinline__ void cpasync16(uint32_t dst, const void* src) {
    asm volatile("cp.async.cg.shared.global [%0], [%1], 16;"
                 :: "r"(dst), "l"(src) : "memory");
}
#define CP_COMMIT() asm volatile("cp.async.commit_group;" ::: "memory")
#define CP_WAIT(n)  asm volatile("cp.async.wait_group %0;" :: "n"(n) : "memory")

__device__ __forceinline__ void ldsm4(uint32_t* r, uint32_t addr) {
    asm volatile("ldmatrix.sync.aligned.m8n8.x4.shared.b16 {%0,%1,%2,%3}, [%4];"
                 : "=r"(r[0]), "=r"(r[1]), "=r"(r[2]), "=r"(r[3]) : "r"(addr));
}
__device__ __forceinline__ void ldsm2(uint32_t* r, uint32_t addr) {
    asm volatile("ldmatrix.sync.aligned.m8n8.x2.shared.b16 {%0,%1}, [%2];"
                 : "=r"(r[0]), "=r"(r[1]) : "r"(addr));
}
__device__ __forceinline__ void mma_f16(float* d, const uint32_t* a, const uint32_t* b) {
    asm volatile("mma.sync.aligned.m16n8k16.row.col.f32.f16.f16.f32 "
                 "{%0,%1,%2,%3}, {%4,%5,%6,%7}, {%8,%9}, {%0,%1,%2,%3};"
                 : "+f"(d[0]), "+f"(d[1]), "+f"(d[2]), "+f"(d[3])
                 : "r"(a[0]), "r"(a[1]), "r"(a[2]), "r"(a[3]),
                   "r"(b[0]), "r"(b[1]));
}

__device__ __forceinline__ float sigf(float x) { return 1.f / (1.f + expf(-x)); }

// ---------------------------------------------------------------------------
// fp16 single-MMA warp-MMA fused GRU step, v4: dual accumulator sets for 2x
// MMA chain ILP (acc for ks=0,32; acc2 for ks=16,48; summed in epilogue).
// CTA tile M=32, N=48 (16 j x 3 gates), K=1024 in 16 chunks of 64.
// Grid (64 j, 8 m) = 512 CTAs; 128 threads = 4 warps as 2m x 2n.
// ---------------------------------------------------------------------------
#define KC 64
#define NCH (Hsz / KC)         // 16
#define NSTAGE 4
#define AROWB 144
#define OFF_A  0u
#define OFF_B  4608u           // 32*144
#define STAGE_B 11520u         // + 48*144
#define DSMEM (NSTAGE * 11520) // 46080
#define GH_STR 52

__global__ __launch_bounds__(128) void gru_step_f16(
    const __half* __restrict__ hhin,
    const float* __restrict__ hprev,
    float*       __restrict__ hout,
    __half* __restrict__ hhout,
    const float* __restrict__ bhh,
    int t)
{
    extern __shared__ __align__(16) char dsmem[];
    const uint32_t sb0 = smem_u32(dsmem);

    const int tid  = threadIdx.x;
    const int wid  = tid >> 5;
    const int lane = tid & 31;
    const int j0   = blockIdx.x << 4;
    const int m0   = blockIdx.y << 5;

    const int wm  = wid & 1;
    const int wn  = wid >> 1;
    const int m0w = wm << 4;
    const int n0w = wn * 24;

    // ---- epilogue operand prefetch (gi fp16)
    float pgr[4], pgz[4], pgn[4], php[4];
#pragma unroll
    for (int it = 0; it < 4; it++) {
        const int flat = tid + (it << 7);
        const int m  = flat >> 4;
        const int jj = flat & 15;
        const int gm = m0 + m;
        const __half* gi = g_GIh + ((size_t)gm * Ssz + t) * G3 + j0 + jj;
        pgr[it] = __half2float(gi[0]);
        pgz[it] = __half2float(gi[Hsz]);
        pgn[it] = __half2float(gi[2 * Hsz]);
        php[it] = hprev[(size_t)gm * Hsz + j0 + jj];
    }

    const int lrow = lane & 7;
    const int tsel = lane >> 3;
    const int arow = ((tsel & 1) << 3) + lrow;
    const int akof = (tsel >> 1) << 3;
    const int brow = lrow;
    const int bkof = ((lane >> 3) & 1) << 3;

    float acc[3][4], acc2[3][4];
#pragma unroll
    for (int j = 0; j < 3; j++)
#pragma unroll
        for (int e = 0; e < 4; e++) { acc[j][e] = 0.f; acc2[j][e] = 0.f; }

    auto load_chunk = [&](int c, int s) {
        const uint32_t sb = sb0 + (uint32_t)s * STAGE_B;
        const int k0 = c * KC;
#pragma unroll
        for (int i = 0; i < 2; i++) {
            const int task = tid + (i << 7);
            const int row = task >> 3, seg = task & 7;
            const size_t src = (size_t)(m0 + row) * Hsz + k0 + seg * 8;
            cpasync16(sb + OFF_A + row * AROWB + seg * 16, hhin + src);
        }
#pragma unroll
        for (int i = 0; i < 3; i++) {
            const int task = tid + (i << 7);
            const int row = task >> 3, seg = task & 7;
            const int gate = row >> 4, jj = row & 15;
            const size_t src = ((size_t)gate * Hsz + j0 + jj) * Hsz + k0 + seg * 8;
            cpasync16(sb + OFF_B + row * AROWB + seg * 16, g_wq + src);
        }
        CP_COMMIT();
    };

#pragma unroll
    for (int c = 0; c < NSTAGE - 1; c++) load_chunk(c, c);

    for (int c = 0; c < NCH; c++) {
        const int s = c & (NSTAGE - 1);
        const int rem = NCH - 1 - c;
        if      (rem >= 2) CP_WAIT(2);
        else if (rem == 1) CP_WAIT(1);
        else               CP_WAIT(0);
        __syncthreads();

        if (c + NSTAGE - 1 < NCH)
            load_chunk(c + NSTAGE - 1, (c + NSTAGE - 1) & (NSTAGE - 1));

        const uint32_t sb = sb0 + (uint32_t)s * STAGE_B;
        const uint32_t aA = sb + OFF_A + (m0w + arow) * AROWB + akof * 2;
        const uint32_t bB = sb + OFF_B + (n0w + brow) * AROWB + bkof * 2;

        // two interleaved half-chunks -> 6 independent MMA chains
#pragma unroll
        for (int ks = 0; ks < KC; ks += 32) {
            uint32_t Aq[4], Bq[3][2], Aq2[4], Bq2[3][2];
            ldsm4(Aq,  aA + ks * 2);
            ldsm4(Aq2, aA + (ks + 16) * 2);
#pragma unroll
            for (int j = 0; j < 3; j++) {
                ldsm2(Bq[j],  bB + j * (8 * AROWB) + ks * 2);
                ldsm2(Bq2[j], bB + j * (8 * AROWB) + (ks + 16) * 2);
            }
#pragma unroll
            for (int j = 0; j < 3; j++) {
                mma_f16(acc[j],  Aq,  Bq[j]);
                mma_f16(acc2[j], Aq2, Bq2[j]);
            }
        }
    }
    __syncthreads();

    float* ghs = reinterpret_cast<float*>(dsmem);
    const int crow = m0w + (lane >> 2);
    const int ccol = n0w + ((lane & 3) << 1);
#pragma unroll
    for (int j = 0; j < 3; j++) {
        const int col = ccol + (j << 3);
        *reinterpret_cast<float2*>(&ghs[crow * GH_STR + col]) =
            make_float2(acc[j][0] + acc2[j][0], acc[j][1] + acc2[j][1]);
        *reinterpret_cast<float2*>(&ghs[(crow + 8) * GH_STR + col]) =
            make_float2(acc[j][2] + acc2[j][2], acc[j][3] + acc2[j][3]);
    }
    __syncthreads();

#pragma unroll
    for (int it = 0; it < 4; it++) {
        const int flat = tid + (it << 7);
        const int m  = flat >> 4;
        const int jj = flat & 15;
        const int j  = j0 + jj;
        const int gm = m0 + m;

        const float ghr = ghs[m * GH_STR + jj]       + bhh[j];
        const float ghz = ghs[m * GH_STR + 16 + jj]  + bhh[Hsz + j];
        const float ghn = ghs[m * GH_STR + 32 + jj]  + bhh[2 * Hsz + j];

        const float r  = sigf(pgr[it] + ghr);
        const float z  = sigf(pgz[it] + ghz);
        const float nn = tanhf(pgn[it] + r * ghn);
        const float hv = (1.f - z) * nn + z * php[it];

        hout[(size_t)gm * Hsz + j] = hv;
        hhout[(size_t)gm * Hsz + j] = __float2half_rn(hv);
    }
}

// ---------------------------------------------------------------------------
// fp16 tensor GEMM for the input-gate GEMMs (K=64 single chunk)
// ---------------------------------------------------------------------------
#define GM_AROWB 144

__global__ __launch_bounds__(256) void gemm_f16_k64(
    const __half* __restrict__ A,     // (rows, 64) padded
    const __half* __restrict__ W,     // (3072, 64) padded
    const float*  __restrict__ bias,  // (3072)
    __half* __restrict__ C)           // (rows, 3072)
{
    __shared__ __align__(16) char sm[2 * 64 * GM_AROWB];
    const uint32_t smA = smem_u32(sm);
    const uint32_t smB = smA + 64 * GM_AROWB;

    const int tid  = threadIdx.x;
    const int wid  = tid >> 5;
    const int lane = tid & 31;
    const int col0 = blockIdx.x << 6;
    const int row0 = blockIdx.y << 6;

    const int wm  = wid & 3;
    const int wn  = wid >> 2;
    const int m0w = wm << 4;
    const int n0w = wn << 5;

#pragma unroll
    for (int i = 0; i < 2; i++) {
        const int task = tid + (i << 8);
        const int row = task >> 3, seg = task & 7;
        cpasync16(smA + row * GM_AROWB + seg * 16,
                  A + (size_t)(row0 + row) * KP + seg * 8);
        cpasync16(smB + row * GM_AROWB + seg * 16,
                  W + (size_t)(col0 + row) * KP + seg * 8);
    }
    CP_COMMIT();

    const int lrow = lane & 7;
    const int tsel = lane >> 3;
    const int arow = ((tsel & 1) << 3) + lrow;
    const int akof = (tsel >> 1) << 3;
    const int brow = lrow;
    const int bkof = ((tsel & 1) << 3);

    float acc[4][4];
#pragma unroll
    for (int j = 0; j < 4; j++)
#pragma unroll
        for (int e = 0; e < 4; e++) acc[j][e] = 0.f;

    CP_WAIT(0);
    __syncthreads();

    const uint32_t aA = smA + (m0w + arow) * GM_AROWB + akof * 2;
    const uint32_t bB = smB + (n0w + brow) * GM_AROWB + bkof * 2;

#pragma unroll
    for (int ks = 0; ks < KP; ks += 16) {
        uint32_t Aq[4], Bq[4][2];
        ldsm4(Aq, aA + ks * 2);
#pragma unroll
        for (int j = 0; j < 4; j++)
            ldsm2(Bq[j], bB + j * (8 * GM_AROWB) + ks * 2);
#pragma unroll
        for (int j = 0; j < 4; j++)
            mma_f16(acc[j], Aq, Bq[j]);
    }

    const int crow = row0 + m0w + (lane >> 2);
    const int ccol0 = col0 + n0w + ((lane & 3) << 1);
#pragma unroll
    for (int j = 0; j < 4; j++) {
        const int col = ccol0 + (j << 3);
        const float b0 = bias[col], b1 = bias[col + 1];
        __half2 v0, v1;
        v0.x = __float2half_rn(acc[j][0] + b0);
        v0.y = __float2half_rn(acc[j][1] + b1);
        v1.x = __float2half_rn(acc[j][2] + b0);
        v1.y = __float2half_rn(acc[j][3] + b1);
        *reinterpret_cast<__half2*>(&C[(size_t)crow * G3 + col]) = v0;
        *reinterpret_cast<__half2*>(&C[(size_t)(crow + 8) * G3 + col]) = v1;
    }
}

// ---------------------------------------------------------------------------
__global__ void quant_whh_kernel(const float* __restrict__ Whh)
{
    const size_t idx = (size_t)blockIdx.x * blockDim.x + threadIdx.x;
    g_wq[idx] = __float2half_rn(Whh[idx]);
}

__global__ void quant_pad63_kernel(const float* __restrict__ src,
                                   __half* __restrict__ dst)
{
    const size_t idx = (size_t)blockIdx.x * blockDim.x + threadIdx.x;
    const size_t row = idx >> 6;
    const int c = (int)(idx & 63);
    dst[idx] = (c < Isz) ? __float2half_rn(src[row * Isz + c]) : __half(0);
}

__global__ void zero_h_kernel()
{
    const int idx = blockIdx.x * blockDim.x + threadIdx.x;
    g_hbuf[0][idx] = 0.f;
    g_hh[0][idx] = __half(0);
}

// ---------------------------------------------------------------------------
// fp32 SGEMM with bias (GH and projector)
__global__ __launch_bounds__(256) void sgemm_bias(
    const float* __restrict__ A, int lda,
    const float* __restrict__ W,
    const float* __restrict__ bias,
    float* __restrict__ C,
    int N, int K)
{
    __shared__ float As[16][64];
    __shared__ float Bsh[16][64];

    const int tid  = threadIdx.x;
    const int tx   = tid & 15;
    const int ty   = tid >> 4;
    const int row0 = blockIdx.y << 6;
    const int col0 = blockIdx.x << 6;

    const int lm = tid >> 2;
    const int lk = (tid & 3) << 2;

    float acc[4][4] = {};

    for (int k0 = 0; k0 < K; k0 += 16) {
#pragma unroll
        for (int c = 0; c < 4; c++) {
            const int k = k0 + lk + c;
            As[lk + c][lm] = (k < K) ? A[(size_t)(row0 + lm) * lda + k] : 0.f;
            const int n = col0 + lm;
            Bsh[lk + c][lm] = (k < K && n < N) ? W[(size_t)n * K + k] : 0.f;
        }
        __syncthreads();

#pragma unroll
        for (int k = 0; k < 16; k++) {
            const float4 av = *reinterpret_cast<const float4*>(&As[k][ty << 2]);
            const float4 bv = *reinterpret_cast<const float4*>(&Bsh[k][tx << 2]);
            const float a[4] = {av.x, av.y, av.z, av.w};
            const float b[4] = {bv.x, bv.y, bv.z, bv.w};
#pragma unroll
            for (int i = 0; i < 4; i++)
#pragma unroll
                for (int j = 0; j < 4; j++)
                    acc[i][j] = fmaf(a[i], b[j], acc[i][j]);
        }
        __syncthreads();
    }

#pragma unroll
    for (int i = 0; i < 4; i++) {
        const int m = row0 + (ty << 2) + i;
#pragma unroll
        for (int j = 0; j < 4; j++) {
            const int n = col0 + (tx << 2) + j;
            if (n < N)
                C[(size_t)m * N + n] = acc[i][j] + bias[n];
        }
    }
}

// Decoder gates (reads fp16 gi)
__global__ void gates_dec_kernel(const float* __restrict__ hfin)
{
    const size_t idx = (size_t)blockIdx.x * blockDim.x + threadIdx.x;
    const int j  = (int)(idx & (Hsz - 1));
    const int bt = (int)(idx >> 10);
    const int b  = bt >> 6;
    const __half* gi = g_G2h + (size_t)bt * G3;
    const float* gh = g_GH + (size_t)b * G3;

    const float r  = sigf(__half2float(gi[j])          + gh[j]);
    const float z  = sigf(__half2float(gi[Hsz + j])    + gh[Hsz + j]);
    const float nn = tanhf(__half2float(gi[2*Hsz + j]) + r * gh[2*Hsz + j]);
    const float hp = hfin[(size_t)b * Hsz + j];
    g_states[idx] = (1.f - z) * nn + z * hp;
}

// ---------------------------------------------------------------------------
extern "C" void kernel_launch(void* const* d_in, const int* in_sizes, int n_in,
                              void* d_out, int out_size)
{
    const float* enc_in  = (const float*)d_in[0];
    const float* dec_in  = (const float*)d_in[1];
    const float* enc_Wih = (const float*)d_in[2];
    const float* enc_Whh = (const float*)d_in[3];
    const float* enc_bih = (const float*)d_in[4];
    const float* enc_bhh = (const float*)d_in[5];
    const float* dec_Wih = (const float*)d_in[6];
    const float* dec_Whh = (const float*)d_in[7];
    const float* dec_bih = (const float*)d_in[8];
    const float* dec_bhh = (const float*)d_in[9];
    const float* proj_W  = (const float*)d_in[10];
    const float* proj_b  = (const float*)d_in[11];
    float* out = (float*)d_out;

    cudaFuncSetAttribute(gru_step_f16,
                         cudaFuncAttributeMaxDynamicSharedMemorySize, DSMEM);

    float *GH, *states, *hbuf;
    __half *GIh, *G2h, *hh, *encin, *decin, *wih1, *wih2;
    cudaGetSymbolAddress((void**)&GIh,    g_GIh);
    cudaGetSymbolAddress((void**)&G2h,    g_G2h);
    cudaGetSymbolAddress((void**)&GH,     g_GH);
    cudaGetSymbolAddress((void**)&states, g_states);
    cudaGetSymbolAddress((void**)&hbuf,   g_hbuf);
    cudaGetSymbolAddress((void**)&hh,     g_hh);
    cudaGetSymbolAddress((void**)&encin,  g_encin_h);
    cudaGetSymbolAddress((void**)&decin,  g_decin_h);
    cudaGetSymbolAddress((void**)&wih1,   g_wih1_h);
    cudaGetSymbolAddress((void**)&wih2,   g_wih2_h);
    float* hf0 = hbuf;
    float* hf1 = hbuf + (size_t)Bsz * Hsz;
    __half* hh0 = hh; __half* hh1 = hh + (size_t)Bsz * Hsz;

    const dim3 blk256(256);

    zero_h_kernel<<<(Bsz * Hsz) / 256, blk256>>>();
    quant_whh_kernel<<<(int)(((size_t)G3 * Hsz) / 256), blk256>>>(enc_Whh);
    quant_pad63_kernel<<<(int)(((size_t)Bsz * Ssz * KP) / 256), blk256>>>(enc_in, encin);
    quant_pad63_kernel<<<(int)(((size_t)Bsz * Tsz * KP) / 256), blk256>>>(dec_in, decin);
    quant_pad63_kernel<<<(int)(((size_t)G3 * KP) / 256), blk256>>>(enc_Wih, wih1);
    quant_pad63_kernel<<<(int)(((size_t)G3 * KP) / 256), blk256>>>(dec_Wih, wih2);

    // Encoder input gates (fp16 tensor GEMM)
    gemm_f16_k64<<<dim3(G3 / 64, (Bsz * Ssz) / 64), blk256>>>(
        encin, wih1, enc_bih, GIh);

    // Encoder recurrence: 128 sequential fp16 1-MMA steps (dual acc sets)
    for (int t = 0; t < Ssz; t++) {
        const int s = t & 1;
        gru_step_f16<<<dim3(Hsz / 16, Bsz / 32), 128, DSMEM>>>(
            s ? hh1 : hh0, s ? hf1 : hf0,
            s ? hf0 : hf1, s ? hh0 : hh1,
            enc_bhh, t);
    }
    float* enc_h = hf0;

    // Decoder hidden-side gates (fp32)
    sgemm_bias<<<dim3(G3 / 64, Bsz / 64), blk256>>>(
        enc_h, Hsz, dec_Whh, dec_bhh, GH, G3, Hsz);

    // Decoder input-side gates (fp16 tensor GEMM)
    gemm_f16_k64<<<dim3(G3 / 64, (Bsz * Tsz) / 64), blk256>>>(
        decin, wih2, dec_bih, G2h);

    // Decoder gates -> states
    gates_dec_kernel<<<(int)(((size_t)Bsz * Tsz * Hsz) / 256), blk256>>>(enc_h);

    // Projector (fp32)
    sgemm_bias<<<dim3((Isz + 63) / 64, (Bsz * Tsz) / 64), blk256>>>(
        states, Hsz, proj_W, proj_b, out, Isz, Hsz);
}

// round 16
// speedup vs baseline: 1.0309x; 1.0309x over previous
#include <cuda_runtime.h>
#include <cuda_fp16.h>
#include <math.h>
#include <stdint.h>

// Problem dims
#define Bsz 256
#define Ssz 128
#define Tsz 64
#define Isz 63
#define Hsz 1024
#define G3  (3*Hsz)   // 3072
#define KP  64        // padded input dim

// Scratch (device globals — no allocations allowed)
__device__ __half g_GIh[(size_t)Bsz * Ssz * G3];    // encoder gi_all fp16
__device__ __half g_G2h[(size_t)Bsz * Tsz * G3];    // decoder gi fp16
__device__ float g_GH[(size_t)Bsz * G3];            // decoder gh (B, 3H)
__device__ float g_states[(size_t)Bsz * Tsz * Hsz]; // decoder states (B*T, H)
__device__ float g_hbuf[2][(size_t)Bsz * Hsz];      // hidden fp32, double buffered
__device__ __half g_hh[2][(size_t)Bsz * Hsz];       // h fp16
__device__ __half g_wq[(size_t)G3 * Hsz];           // enc Whh fp16
__device__ __half g_encin_h[(size_t)Bsz * Ssz * KP];// enc inputs fp16, padded K=64
__device__ __half g_decin_h[(size_t)Bsz * Tsz * KP];// dec inputs fp16, padded
__device__ __half g_wih1_h[(size_t)G3 * KP];        // enc Wih fp16, padded
__device__ __half g_wih2_h[(size_t)G3 * KP];        // dec Wih fp16, padded

// ---------------------------------------------------------------------------
__device__ __forceinline__ uint32_t smem_u32(const void* p) {
    uint32_t a;
    asm("{ .reg .u64 t; cvta.to.shared.u64 t, %1; cvt.u32.u64 %0, t; }"
        : "=r"(a) : "l"(p));
    return a;
}
__device__ __forceinline__ void cpasync16(uint32_t dst, const void* src) {
    asm volatile("cp.async.cg.shared.global [%0], [%1], 16;"
                 :: "r"(dst), "l"(src) : "memory");
}
#define CP_COMMIT() asm volatile("cp.async.commit_group;" ::: "memory")
#define CP_WAIT(n)  asm volatile("cp.async.wait_group %0;" :: "n"(n) : "memory")

__device__ __forceinline__ void ldsm4(uint32_t* r, uint32_t addr) {
    asm volatile("ldmatrix.sync.aligned.m8n8.x4.shared.b16 {%0,%1,%2,%3}, [%4];"
                 : "=r"(r[0]), "=r"(r[1]), "=r"(r[2]), "=r"(r[3]) : "r"(addr));
}
__device__ __forceinline__ void ldsm2(uint32_t* r, uint32_t addr) {
    asm volatile("ldmatrix.sync.aligned.m8n8.x2.shared.b16 {%0,%1}, [%2];"
                 : "=r"(r[0]), "=r"(r[1]) : "r"(addr));
}
__device__ __forceinline__ void mma_f16(float* d, const uint32_t* a, const uint32_t* b) {
    asm volatile("mma.sync.aligned.m16n8k16.row.col.f32.f16.f16.f32 "
                 "{%0,%1,%2,%3}, {%4,%5,%6,%7}, {%8,%9}, {%0,%1,%2,%3};"
                 : "+f"(d[0]), "+f"(d[1]), "+f"(d[2]), "+f"(d[3])
                 : "r"(a[0]), "r"(a[1]), "r"(a[2]), "r"(a[3]),
                   "r"(b[0]), "r"(b[1]));
}

__device__ __forceinline__ float sigf(float x) { return 1.f / (1.f + expf(-x)); }

// ---------------------------------------------------------------------------
// fp16 single-MMA warp-MMA fused GRU step, v5 (R14 base + overhead cuts):
//  - NSTAGE=3 (2 chunks in flight; faster prologue fill)
//  - gh dump region separate from stages (one fewer barrier at tail)
//  - pipeline started before epilogue-operand prefetch
//  - bhh prefetched into registers in prologue
// CTA tile M=32, N=48 (16 j x 3 gates), K=1024 in 16 chunks of 64.
// Grid (64 j, 8 m) = 512 CTAs; 128 threads = 4 warps as 2m x 2n.
// ---------------------------------------------------------------------------
#define KC 64
#define NCH (Hsz / KC)          // 16
#define NSTAGE 3
#define AROWB 144
#define OFF_A  0u
#define OFF_B  4608u            // 32*144
#define STAGE_B 11520u          // + 48*144
#define GHS_OFF (3 * 11520)     // 34560 (after the 3 stages)
#define DSMEM (GHS_OFF + 32 * 52 * 4)   // 41216 (<48KB)
#define GH_STR 52

__global__ __launch_bounds__(128) void gru_step_f16(
    const __half* __restrict__ hhin,
    const float* __restrict__ hprev,
    float*       __restrict__ hout,
    __half* __restrict__ hhout,
    const float* __restrict__ bhh,
    int t)
{
    extern __shared__ __align__(16) char dsmem[];
    const uint32_t sb0 = smem_u32(dsmem);

    const int tid  = threadIdx.x;
    const int wid  = tid >> 5;
    const int lane = tid & 31;
    const int j0   = blockIdx.x << 4;
    const int m0   = blockIdx.y << 5;

    const int wm  = wid & 1;
    const int wn  = wid >> 1;
    const int m0w = wm << 4;
    const int n0w = wn * 24;

    auto load_chunk = [&](int c, int s) {
        const uint32_t sb = sb0 + (uint32_t)s * STAGE_B;
        const int k0 = c * KC;
#pragma unroll
        for (int i = 0; i < 2; i++) {
            const int task = tid + (i << 7);
            const int row = task >> 3, seg = task & 7;
            const size_t src = (size_t)(m0 + row) * Hsz + k0 + seg * 8;
            cpasync16(sb + OFF_A + row * AROWB + seg * 16, hhin + src);
        }
#pragma unroll
        for (int i = 0; i < 3; i++) {
            const int task = tid + (i << 7);
            const int row = task >> 3, seg = task & 7;
            const int gate = row >> 4, jj = row & 15;
            const size_t src = ((size_t)gate * Hsz + j0 + jj) * Hsz + k0 + seg * 8;
            cpasync16(sb + OFF_B + row * AROWB + seg * 16, g_wq + src);
        }
        CP_COMMIT();
    };

    // start the pipeline FIRST (2 chunks in flight)
    load_chunk(0, 0);
    load_chunk(1, 1);

    // ---- epilogue operand prefetch (issued behind the pipeline)
    float pgr[4], pgz[4], pgn[4], php[4], pbr[4], pbz[4], pbn[4];
#pragma unroll
    for (int it = 0; it < 4; it++) {
        const int flat = tid + (it << 7);
        const int m  = flat >> 4;
        const int jj = flat & 15;
        const int gm = m0 + m;
        const int j  = j0 + jj;
        const __half* gi = g_GIh + ((size_t)gm * Ssz + t) * G3 + j;
        pgr[it] = __half2float(gi[0]);
        pgz[it] = __half2float(gi[Hsz]);
        pgn[it] = __half2float(gi[2 * Hsz]);
        php[it] = hprev[(size_t)gm * Hsz + j];
        pbr[it] = bhh[j];
        pbz[it] = bhh[Hsz + j];
        pbn[it] = bhh[2 * Hsz + j];
    }

    const int lrow = lane & 7;
    const int tsel = lane >> 3;
    const int arow = ((tsel & 1) << 3) + lrow;
    const int akof = (tsel >> 1) << 3;
    const int brow = lrow;
    const int bkof = ((lane >> 3) & 1) << 3;

    float acc[3][4];
#pragma unroll
    for (int j = 0; j < 3; j++)
#pragma unroll
        for (int e = 0; e < 4; e++) acc[j][e] = 0.f;

    int s = 0;       // stage of chunk c
    int sw = 2;      // stage to write (chunk c+2)
    for (int c = 0; c < NCH; c++) {
        if (c + 1 < NCH) CP_WAIT(1);
        else             CP_WAIT(0);
        __syncthreads();   // publishes chunk c; proves compute c-1 done

        if (c + 2 < NCH) load_chunk(c + 2, sw);

        const uint32_t sb = sb0 + (uint32_t)s * STAGE_B;
        const uint32_t aA = sb + OFF_A + (m0w + arow) * AROWB + akof * 2;
        const uint32_t bB = sb + OFF_B + (n0w + brow) * AROWB + bkof * 2;

#pragma unroll
        for (int ks = 0; ks < KC; ks += 16) {
            uint32_t Aq[4], Bq[3][2];
            ldsm4(Aq, aA + ks * 2);
#pragma unroll
            for (int j = 0; j < 3; j++)
                ldsm2(Bq[j], bB + j * (8 * AROWB) + ks * 2);
#pragma unroll
            for (int j = 0; j < 3; j++)
                mma_f16(acc[j], Aq, Bq[j]);
        }
        // advance stage counters (mod 3)
        s  = (s  == 2) ? 0 : s + 1;
        sw = (sw == 2) ? 0 : sw + 1;
    }

    // ---- dump gh to the DEDICATED smem region (no barrier needed before)
    float* ghs = reinterpret_cast<float*>(dsmem + GHS_OFF);
    const int crow = m0w + (lane >> 2);
    const int ccol = n0w + ((lane & 3) << 1);
#pragma unroll
    for (int j = 0; j < 3; j++) {
        const int col = ccol + (j << 3);
        *reinterpret_cast<float2*>(&ghs[crow * GH_STR + col]) =
            make_float2(acc[j][0], acc[j][1]);
        *reinterpret_cast<float2*>(&ghs[(crow + 8) * GH_STR + col]) =
            make_float2(acc[j][2], acc[j][3]);
    }
    __syncthreads();

    // ---- GRU gates: 512 (m, jj) pairs, 4 per thread (all operands in regs)
#pragma unroll
    for (int it = 0; it < 4; it++) {
        const int flat = tid + (it << 7);
        const int m  = flat >> 4;
        const int jj = flat & 15;
        const int j  = j0 + jj;
        const int gm = m0 + m;

        const float ghr = ghs[m * GH_STR + jj]       + pbr[it];
        const float ghz = ghs[m * GH_STR + 16 + jj]  + pbz[it];
        const float ghn = ghs[m * GH_STR + 32 + jj]  + pbn[it];

        const float r  = sigf(pgr[it] + ghr);
        const float z  = sigf(pgz[it] + ghz);
        const float nn = tanhf(pgn[it] + r * ghn);
        const float hv = (1.f - z) * nn + z * php[it];

        hout[(size_t)gm * Hsz + j] = hv;
        hhout[(size_t)gm * Hsz + j] = __float2half_rn(hv);
    }
}

// ---------------------------------------------------------------------------
// fp16 tensor GEMM for the input-gate GEMMs (K=64 single chunk)
// ---------------------------------------------------------------------------
#define GM_AROWB 144

__global__ __launch_bounds__(256) void gemm_f16_k64(
    const __half* __restrict__ A,     // (rows, 64) padded
    const __half* __restrict__ W,     // (3072, 64) padded
    const float*  __restrict__ bias,  // (3072)
    __half* __restrict__ C)           // (rows, 3072)
{
    __shared__ __align__(16) char sm[2 * 64 * GM_AROWB];
    const uint32_t smA = smem_u32(sm);
    const uint32_t smB = smA + 64 * GM_AROWB;

    const int tid  = threadIdx.x;
    const int wid  = tid >> 5;
    const int lane = tid & 31;
    const int col0 = blockIdx.x << 6;
    const int row0 = blockIdx.y << 6;

    const int wm  = wid & 3;
    const int wn  = wid >> 2;
    const int m0w = wm << 4;
    const int n0w = wn << 5;

#pragma unroll
    for (int i = 0; i < 2; i++) {
        const int task = tid + (i << 8);
        const int row = task >> 3, seg = task & 7;
        cpasync16(smA + row * GM_AROWB + seg * 16,
                  A + (size_t)(row0 + row) * KP + seg * 8);
        cpasync16(smB + row * GM_AROWB + seg * 16,
                  W + (size_t)(col0 + row) * KP + seg * 8);
    }
    CP_COMMIT();

    const int lrow = lane & 7;
    const int tsel = lane >> 3;
    const int arow = ((tsel & 1) << 3) + lrow;
    const int akof = (tsel >> 1) << 3;
    const int brow = lrow;
    const int bkof = ((tsel & 1) << 3);

    float acc[4][4];
#pragma unroll
    for (int j = 0; j < 4; j++)
#pragma unroll
        for (int e = 0; e < 4; e++) acc[j][e] = 0.f;

    CP_WAIT(0);
    __syncthreads();

    const uint32_t aA = smA + (m0w + arow) * GM_AROWB + akof * 2;
    const uint32_t bB = smB + (n0w + brow) * GM_AROWB + bkof * 2;

#pragma unroll
    for (int ks = 0; ks < KP; ks += 16) {
        uint32_t Aq[4], Bq[4][2];
        ldsm4(Aq, aA + ks * 2);
#pragma unroll
        for (int j = 0; j < 4; j++)
            ldsm2(Bq[j], bB + j * (8 * GM_AROWB) + ks * 2);
#pragma unroll
        for (int j = 0; j < 4; j++)
            mma_f16(acc[j], Aq, Bq[j]);
    }

    const int crow = row0 + m0w + (lane >> 2);
    const int ccol0 = col0 + n0w + ((lane & 3) << 1);
#pragma unroll
    for (int j = 0; j < 4; j++) {
        const int col = ccol0 + (j << 3);
        const float b0 = bias[col], b1 = bias[col + 1];
        __half2 v0, v1;
        v0.x = __float2half_rn(acc[j][0] + b0);
        v0.y = __float2half_rn(acc[j][1] + b1);
        v1.x = __float2half_rn(acc[j][2] + b0);
        v1.y = __float2half_rn(acc[j][3] + b1);
        *reinterpret_cast<__half2*>(&C[(size_t)crow * G3 + col]) = v0;
        *reinterpret_cast<__half2*>(&C[(size_t)(crow + 8) * G3 + col]) = v1;
    }
}

// ---------------------------------------------------------------------------
__global__ void quant_whh_kernel(const float* __restrict__ Whh)
{
    const size_t idx = (size_t)blockIdx.x * blockDim.x + threadIdx.x;
    g_wq[idx] = __float2half_rn(Whh[idx]);
}

__global__ void quant_pad63_kernel(const float* __restrict__ src,
                                   __half* __restrict__ dst)
{
    const size_t idx = (size_t)blockIdx.x * blockDim.x + threadIdx.x;
    const size_t row = idx >> 6;
    const int c = (int)(idx & 63);
    dst[idx] = (c < Isz) ? __float2half_rn(src[row * Isz + c]) : __half(0);
}

__global__ void zero_h_kernel()
{
    const int idx = blockIdx.x * blockDim.x + threadIdx.x;
    g_hbuf[0][idx] = 0.f;
    g_hh[0][idx] = __half(0);
}

// ---------------------------------------------------------------------------
// fp32 SGEMM with bias (GH and projector)
__global__ __launch_bounds__(256) void sgemm_bias(
    const float* __restrict__ A, int lda,
    const float* __restrict__ W,
    const float* __restrict__ bias,
    float* __restrict__ C,
    int N, int K)
{
    __shared__ float As[16][64];
    __shared__ float Bsh[16][64];

    const int tid  = threadIdx.x;
    const int tx   = tid & 15;
    const int ty   = tid >> 4;
    const int row0 = blockIdx.y << 6;
    const int col0 = blockIdx.x << 6;

    const int lm = tid >> 2;
    const int lk = (tid & 3) << 2;

    float acc[4][4] = {};

    for (int k0 = 0; k0 < K; k0 += 16) {
#pragma unroll
        for (int c = 0; c < 4; c++) {
            const int k = k0 + lk + c;
            As[lk + c][lm] = (k < K) ? A[(size_t)(row0 + lm) * lda + k] : 0.f;
            const int n = col0 + lm;
            Bsh[lk + c][lm] = (k < K && n < N) ? W[(size_t)n * K + k] : 0.f;
        }
        __syncthreads();

#pragma unroll
        for (int k = 0; k < 16; k++) {
            const float4 av = *reinterpret_cast<const float4*>(&As[k][ty << 2]);
            const float4 bv = *reinterpret_cast<const float4*>(&Bsh[k][tx << 2]);
            const float a[4] = {av.x, av.y, av.z, av.w};
            const float b[4] = {bv.x, bv.y, bv.z, bv.w};
#pragma unroll
            for (int i = 0; i < 4; i++)
#pragma unroll
                for (int j = 0; j < 4; j++)
                    acc[i][j] = fmaf(a[i], b[j], acc[i][j]);
        }
        __syncthreads();
    }

#pragma unroll
    for (int i = 0; i < 4; i++) {
        const int m = row0 + (ty << 2) + i;
#pragma unroll
        for (int j = 0; j < 4; j++) {
            const int n = col0 + (tx << 2) + j;
            if (n < N)
                C[(size_t)m * N + n] = acc[i][j] + bias[n];
        }
    }
}

// Decoder gates (reads fp16 gi)
__global__ void gates_dec_kernel(const float* __restrict__ hfin)
{
    const size_t idx = (size_t)blockIdx.x * blockDim.x + threadIdx.x;
    const int j  = (int)(idx & (Hsz - 1));
    const int bt = (int)(idx >> 10);
    const int b  = bt >> 6;
    const __half* gi = g_G2h + (size_t)bt * G3;
    const float* gh = g_GH + (size_t)b * G3;

    const float r  = sigf(__half2float(gi[j])          + gh[j]);
    const float z  = sigf(__half2float(gi[Hsz + j])    + gh[Hsz + j]);
    const float nn = tanhf(__half2float(gi[2*Hsz + j]) + r * gh[2*Hsz + j]);
    const float hp = hfin[(size_t)b * Hsz + j];
    g_states[idx] = (1.f - z) * nn + z * hp;
}

// ---------------------------------------------------------------------------
extern "C" void kernel_launch(void* const* d_in, const int* in_sizes, int n_in,
                              void* d_out, int out_size)
{
    const float* enc_in  = (const float*)d_in[0];
    const float* dec_in  = (const float*)d_in[1];
    const float* enc_Wih = (const float*)d_in[2];
    const float* enc_Whh = (const float*)d_in[3];
    const float* enc_bih = (const float*)d_in[4];
    const float* enc_bhh = (const float*)d_in[5];
    const float* dec_Wih = (const float*)d_in[6];
    const float* dec_Whh = (const float*)d_in[7];
    const float* dec_bih = (const float*)d_in[8];
    const float* dec_bhh = (const float*)d_in[9];
    const float* proj_W  = (const float*)d_in[10];
    const float* proj_b  = (const float*)d_in[11];
    float* out = (float*)d_out;

    float *GH, *states, *hbuf;
    __half *GIh, *G2h, *hh, *encin, *decin, *wih1, *wih2;
    cudaGetSymbolAddress((void**)&GIh,    g_GIh);
    cudaGetSymbolAddress((void**)&G2h,    g_G2h);
    cudaGetSymbolAddress((void**)&GH,     g_GH);
    cudaGetSymbolAddress((void**)&states, g_states);
    cudaGetSymbolAddress((void**)&hbuf,   g_hbuf);
    cudaGetSymbolAddress((void**)&hh,     g_hh);
    cudaGetSymbolAddress((void**)&encin,  g_encin_h);
    cudaGetSymbolAddress((void**)&decin,  g_decin_h);
    cudaGetSymbolAddress((void**)&wih1,   g_wih1_h);
    cudaGetSymbolAddress((void**)&wih2,   g_wih2_h);
    float* hf0 = hbuf;
    float* hf1 = hbuf + (size_t)Bsz * Hsz;
    __half* hh0 = hh; __half* hh1 = hh + (size_t)Bsz * Hsz;

    const dim3 blk256(256);

    zero_h_kernel<<<(Bsz * Hsz) / 256, blk256>>>();
    quant_whh_kernel<<<(int)(((size_t)G3 * Hsz) / 256), blk256>>>(enc_Whh);
    quant_pad63_kernel<<<(int)(((size_t)Bsz * Ssz * KP) / 256), blk256>>>(enc_in, encin);
    quant_pad63_kernel<<<(int)(((size_t)Bsz * Tsz * KP) / 256), blk256>>>(dec_in, decin);
    quant_pad63_kernel<<<(int)(((size_t)G3 * KP) / 256), blk256>>>(enc_Wih, wih1);
    quant_pad63_kernel<<<(int)(((size_t)G3 * KP) / 256), blk256>>>(dec_Wih, wih2);

    // Encoder input gates (fp16 tensor GEMM)
    gemm_f16_k64<<<dim3(G3 / 64, (Bsz * Ssz) / 64), blk256>>>(
        encin, wih1, enc_bih, GIh);

    // Encoder recurrence: 128 sequential fp16 1-MMA steps
    for (int t = 0; t < Ssz; t++) {
        const int s = t & 1;
        gru_step_f16<<<dim3(Hsz / 16, Bsz / 32), 128, DSMEM>>>(
            s ? hh1 : hh0, s ? hf1 : hf0,
            s ? hf0 : hf1, s ? hh0 : hh1,
            enc_bhh, t);
    }
    float* enc_h = hf0;

    // Decoder hidden-side gates (fp32)
    sgemm_bias<<<dim3(G3 / 64, Bsz / 64), blk256>>>(
        enc_h, Hsz, dec_Whh, dec_bhh, GH, G3, Hsz);

    // Decoder input-side gates (fp16 tensor GEMM)
    gemm_f16_k64<<<dim3(G3 / 64, (Bsz * Tsz) / 64), blk256>>>(
        decin, wih2, dec_bih, G2h);

    // Decoder gates -> states
    gates_dec_kernel<<<(int)(((size_t)Bsz * Tsz * Hsz) / 256), blk256>>>(enc_h);

    // Projector (fp32)
    sgemm_bias<<<dim3((Isz + 63) / 64, (Bsz * Tsz) / 64), blk256>>>(
        states, Hsz, proj_W, proj_b, out, Isz, Hsz);
}